// round 15
// baseline (speedup 1.0000x reference)
#include <cuda_runtime.h>
#include <cstdint>

// BKT 2-state HMM forward-backward, FULLY FUSED: one block (64 thr) = one row.
// Warp-shuffle Kogge-Stone over 64 time segments (L=16 steps each):
// 5 in-warp rounds + single cross-warp fold. Scan cost amortized over 2x elements.
// corr: (B,T) int32 ; dynamics_logits: (B,3) f32 ; obs_logits: (B,T,2) f32
// out: (3,B,T,2) f32 = [output_logprobs, state_posteriors, smoothed]

#define BN   8192
#define TT   1024
#define SEG  64
#define L    16
#define LN2F 0.69314718055994531f
#define FULL 0xFFFFFFFFu

__device__ __forceinline__ float frcp(float x) {
    float r;
    asm("rcp.approx.f32 %0, %1;" : "=f"(r) : "f"(x));
    return r;
}

// 2x2 matmul, layout x=m00 y=m01 z=m10 w=m11 ; returns A*B
__device__ __forceinline__ float4 mm2(float4 A, float4 B) {
    return make_float4(A.x * B.x + A.y * B.z,
                       A.x * B.y + A.y * B.w,
                       A.z * B.x + A.w * B.z,
                       A.z * B.y + A.w * B.w);
}

__device__ __forceinline__ void renormE(float4& M, int& E) {
    float s = (M.x + M.y) + (M.z + M.w);
    int eb = (__float_as_int(s) >> 23) & 0xFF;
    float sc = __int_as_float((254 - eb) << 23);
    M.x *= sc; M.y *= sc; M.z *= sc; M.w *= sc;
    E += eb - 127;
}
__device__ __forceinline__ void renormD(float4& M) {
    float s = (M.x + M.y) + (M.z + M.w);
    int eb = (__float_as_int(s) >> 23) & 0xFF;
    float sc = __int_as_float((254 - eb) << 23);
    M.x *= sc; M.y *= sc; M.z *= sc; M.w *= sc;
}

__device__ __forceinline__ float4 shflup4(float4 v, int d) {
    return make_float4(__shfl_up_sync(FULL, v.x, d),
                       __shfl_up_sync(FULL, v.y, d),
                       __shfl_up_sync(FULL, v.z, d),
                       __shfl_up_sync(FULL, v.w, d));
}
__device__ __forceinline__ float4 shfldn4(float4 v, int d) {
    return make_float4(__shfl_down_sync(FULL, v.x, d),
                       __shfl_down_sync(FULL, v.y, d),
                       __shfl_down_sync(FULL, v.z, d),
                       __shfl_down_sync(FULL, v.w, d));
}

__global__ __launch_bounds__(64, 8)
void bkt_fused(const int* __restrict__ corr,
               const float* __restrict__ dyn,
               const float* __restrict__ obs,
               float* __restrict__ out)
{
    __shared__ float4 sWa[2];  __shared__ int sEWa[2];  // alpha warp-total
    __shared__ float4 sWb[2];                            // beta warp-total (transposed)
    // staging: [(pair)*65 + seg], pair=0..7, seg=0..63 -> conflict-free STS & LDS
    __shared__ float4 sP4[8 * 65];   // pred
    __shared__ float4 sQ4[8 * 65];   // post
    __shared__ float4 sS4[8 * 65];   // smoothed

    const int k    = threadIdx.x;      // segment index in row (0..63)
    const int lane = k & 31;
    const int w    = k >> 5;
    const int row  = blockIdx.x;

    // ---------------- load own segment (128B obs, 64B corr per thread) ----------------
    float o[2 * L];
    const float4* op = (const float4*)(obs + (size_t)row * (TT * 2) + k * (2 * L));
#pragma unroll
    for (int i = 0; i < 8; i++) {
        float4 v = op[i];
        o[4 * i + 0] = v.x; o[4 * i + 1] = v.y;
        o[4 * i + 2] = v.z; o[4 * i + 3] = v.w;
    }
    unsigned ymask = 0;
    const int4* cp = (const int4*)(corr + (size_t)row * TT + k * L);
#pragma unroll
    for (int i = 0; i < 4; i++) {
        int4 v = cp[i];
        ymask |= (unsigned)(v.x & 1) << (4 * i + 0);
        ymask |= (unsigned)(v.y & 1) << (4 * i + 1);
        ymask |= (unsigned)(v.z & 1) << (4 * i + 2);
        ymask |= (unsigned)(v.w & 1) << (4 * i + 3);
    }

    // per-row parameters (broadcast loads); shared rcp for the two trans sigmoids
    float d0 = dyn[row * 3 + 0];
    float d1 = dyn[row * 3 + 1];
    float d2 = dyn[row * 3 + 2];
    float ed0 = __expf(d0), ed1 = __expf(d1), ed2 = __expf(d2);
    float q0d = 1.f + ed0, q1d = 1.f + ed1;
    float rpd = frcp(q0d * q1d);
    float rr0 = rpd * q1d;            // 1/(1+ed0)
    float rr1 = rpd * q0d;            // 1/(1+ed1)
    float ri2 = frcp(1.f + ed2);
    float t00 = rr0,       t10 = ed0 * rr0;   // src=0 column (sums to 1)
    float t01 = ed1 * rr1, t11 = rr1;         // src=1 column (sums to 1)
    float ai0 = ri2, ai1 = ed2 * ri2;         // normalized alpha_init

    // ---------------- phase 1: emissions + segment 2x2 product (mid renorm) ----------------
    float4 A = make_float4(1.f, 0.f, 0.f, 1.f);
    int Ea = 0;
#pragma unroll
    for (int j = 0; j < L; j++) {
        int y = (ymask >> j) & 1;
        float e0 = __expf(o[2 * j]), e1 = __expf(o[2 * j + 1]);
        float s0 = 1.f + e0, s1 = 1.f + e1;
        float rp = frcp(s0 * s1);
        float r0 = rp * s1;           // 1/(1+e0)
        float r1 = rp * s0;           // 1/(1+e1)
        float py0 = y ? e0 * r0 : r0;
        float py1 = y ? r1 : e1 * r1;
        o[2 * j]     = py0;           // keep emissions in registers
        o[2 * j + 1] = py1;

        float m00 = t00 * py0, m01 = t01 * py1;
        float m10 = t10 * py0, m11 = t11 * py1;
        A = make_float4(m00 * A.x + m01 * A.z,
                        m00 * A.y + m01 * A.w,
                        m10 * A.x + m11 * A.z,
                        m10 * A.y + m11 * A.w);
        if (j == 7) renormE(A, Ea);   // guard against 16-step underflow
    }
    renormE(A, Ea);

    // ---------------- phase 2a: in-warp shuffle scans ----------------
    float4 va = A;  int ea = Ea;                     // prefix: va_k = A_k ... A_first
    float4 vb = make_float4(A.x, A.z, A.y, A.w);     // suffix of A^T
#pragma unroll
    for (int d = 1; d < 32; d <<= 1) {
        float4 na = shflup4(va, d);
        int   nea = __shfl_up_sync(FULL, ea, d);
        float4 nb = shfldn4(vb, d);
        if (lane >= d)      { va = mm2(va, na); ea += nea; renormE(va, ea); }
        if (lane + d < 32)  { vb = mm2(vb, nb); renormD(vb); }
    }
    if (lane == 31) { sWa[w] = va; sEWa[w] = ea; }
    if (lane == 0)  { sWb[w] = vb; }
    __syncthreads();

    // ---------------- phase 2b: cross-warp combine (2 warps -> single fold) ----------------
    float u0 = ai0, u1 = ai1; int Eu = 0;
    if (w == 1) {
        float4 W = sWa[0];
        float n0 = W.x * u0 + W.y * u1;
        float n1 = W.z * u0 + W.w * u1;
        float s  = n0 + n1;
        int eb = (__float_as_int(s) >> 23) & 0xFF;
        float sc = __int_as_float((254 - eb) << 23);
        u0 = n0 * sc; u1 = n1 * sc;
        Eu = sEWa[0] + (eb - 127);
    }
    float wv0 = 1.f, wv1 = 1.f;
    if (w == 0) {
        float4 W = sWb[1];
        float n0 = W.x + W.y;        // W * ones
        float n1 = W.z + W.w;
        float rs = frcp(n0 + n1);
        wv0 = n0 * rs; wv1 = n1 * rs;
    }

    float4 exv = shflup4(va, 1);
    int    exe = __shfl_up_sync(FULL, ea, 1);
    float4 exb = shfldn4(vb, 1);

    float a0, a1, C;
    if (lane == 0) {
        float s  = u0 + u1;
        float rs = frcp(s);
        a0 = u0 * rs; a1 = u1 * rs;
        C = __logf(s) + (float)Eu * LN2F;
    } else {
        float v0 = exv.x * u0 + exv.y * u1;
        float v1 = exv.z * u0 + exv.w * u1;
        float s  = v0 + v1;
        float rs = frcp(s);
        a0 = v0 * rs; a1 = v1 * rs;
        C = __logf(s) + (float)(exe + Eu) * LN2F;
    }
    float b0, b1;
    if (lane == 31) {
        b0 = wv0; b1 = wv1;
    } else {
        b0 = exb.x * wv0 + exb.y * wv1;
        b1 = exb.z * wv0 + exb.w * wv1;
    }

    // ---------------- phase 3: outputs (pair-accumulated, STS.128) ----------------
    float f0s[L];
    float hp0 = 0.f, hp1 = 0.f, hq0 = 0.f, hq1 = 0.f;
#pragma unroll
    for (int j = 0; j < L; j++) {
        int y = (ymask >> j) & 1;
        float py0 = o[2 * j];
        float py1 = o[2 * j + 1];

        float jj0 = a0 * py0;
        float jj1 = a1 * py1;
        float js  = jj0 + jj1;           // predictive prob of observed symbol
        float ljs = __logf(js);
        float lns = __logf(1.f - js);    // predictive probs sum to 1 (a normalized)
        float lp0 = y ? lns : ljs;
        float lp1 = y ? ljs : lns;
        float po0 = __logf(jj0) + C;
        float po1 = __logf(jj1) + C;

        float f  = jj0 * frcp(js);
        f0s[j] = f;
        float fc = 1.f - f;
        a0 = t00 * f + t01 * fc;         // stays normalized (T columns sum to 1)
        a1 = t10 * f + t11 * fc;
        C += ljs;

        if ((j & 1) == 0) {
            hp0 = lp0; hp1 = lp1; hq0 = po0; hq1 = po1;
        } else {
            sP4[(j >> 1) * 65 + k] = make_float4(hp0, hp1, lp0, lp1);
            sQ4[(j >> 1) * 65 + k] = make_float4(hq0, hq1, po0, po1);
        }
    }
    // backward: smoothed (descending; odd j held, stored at even j); mid renorm of beta
    float hs0 = 0.f, hs1 = 0.f;
#pragma unroll
    for (int j = L - 1; j >= 0; j--) {
        float f  = f0s[j];
        float fc = 1.f - f;
        float g0 = f  * b0;
        float g1 = fc * b1;
        float rg = frcp(g0 + g1);
        float s0 = __logf(g0 * rg);
        float s1 = __logf(g1 * rg);

        if (j & 1) {
            hs0 = s0; hs1 = s1;
        } else {
            sS4[(j >> 1) * 65 + k] = make_float4(s0, s1, hs0, hs1);
        }

        float u0b = o[2 * j]     * b0;
        float u1b = o[2 * j + 1] * b1;
        b0 = t00 * u0b + t10 * u1b;      // beta to t-1
        b1 = t01 * u0b + t11 * u1b;
        if (j == 8) {                    // pow2 rescale: beta scale-invariant for smoothed
            float sb = b0 + b1;
            int eb = (__float_as_int(sb) >> 23) & 0xFF;
            float sc = __int_as_float((254 - eb) << 23);
            b0 *= sc; b1 *= sc;
        }
    }
    __syncthreads();

    // ---------------- flush: LDS.128 -> fully-coalesced STG.128 ----------------
    float4* dP = (float4*)(out + (size_t)row * (TT * 2));
    float4* dQ = (float4*)(out + (size_t)BN * TT * 2 + (size_t)row * (TT * 2));
    float4* dS = (float4*)(out + (size_t)2 * BN * TT * 2 + (size_t)row * (TT * 2));
#pragma unroll
    for (int i = 0; i < 8; i++) {
        int G = i * 64 + k;              // float4 index within row (0..511)
        int m = (G & 7) * 65 + (G >> 3); // seg = G>>3, pair = G&7
        dP[G] = sP4[m];
        dQ[G] = sQ4[m];
        dS[G] = sS4[m];
    }
}

extern "C" void kernel_launch(void* const* d_in, const int* in_sizes, int n_in,
                              void* d_out, int out_size)
{
    const int*   corr = (const int*)d_in[0];
    const float* dyn  = (const float*)d_in[1];
    const float* obs  = (const float*)d_in[2];
    float* out = (float*)d_out;

    bkt_fused<<<BN, 64>>>(corr, dyn, obs, out);
}

// round 16
// speedup vs baseline: 1.0848x; 1.0848x over previous
#include <cuda_runtime.h>
#include <cstdint>

// BKT 2-state HMM forward-backward, FULLY FUSED: one block = one row.
// Warp-shuffle Kogge-Stone over 128 time segments (L=8 steps each).
// f0 parked in smem (off critical chain) to cut regs -> 7 blocks/SM.
// pred/post flushed between fwd and bwd loops to spread DRAM traffic.
// corr: (B,T) int32 ; dynamics_logits: (B,3) f32 ; obs_logits: (B,T,2) f32
// out: (3,B,T,2) f32 = [output_logprobs, state_posteriors, smoothed]

#define BN   8192
#define TT   1024
#define SEG  128
#define L    8
#define LN2F 0.69314718055994531f
#define FULL 0xFFFFFFFFu

__device__ __forceinline__ float frcp(float x) {
    float r;
    asm("rcp.approx.f32 %0, %1;" : "=f"(r) : "f"(x));
    return r;
}

// 2x2 matmul, layout x=m00 y=m01 z=m10 w=m11 ; returns A*B
__device__ __forceinline__ float4 mm2(float4 A, float4 B) {
    return make_float4(A.x * B.x + A.y * B.z,
                       A.x * B.y + A.y * B.w,
                       A.z * B.x + A.w * B.z,
                       A.z * B.y + A.w * B.w);
}

__device__ __forceinline__ void renormE(float4& M, int& E) {
    float s = (M.x + M.y) + (M.z + M.w);
    int eb = (__float_as_int(s) >> 23) & 0xFF;
    float sc = __int_as_float((254 - eb) << 23);
    M.x *= sc; M.y *= sc; M.z *= sc; M.w *= sc;
    E += eb - 127;
}
__device__ __forceinline__ void renormD(float4& M) {
    float s = (M.x + M.y) + (M.z + M.w);
    int eb = (__float_as_int(s) >> 23) & 0xFF;
    float sc = __int_as_float((254 - eb) << 23);
    M.x *= sc; M.y *= sc; M.z *= sc; M.w *= sc;
}

__device__ __forceinline__ float4 shflup4(float4 v, int d) {
    return make_float4(__shfl_up_sync(FULL, v.x, d),
                       __shfl_up_sync(FULL, v.y, d),
                       __shfl_up_sync(FULL, v.z, d),
                       __shfl_up_sync(FULL, v.w, d));
}
__device__ __forceinline__ float4 shfldn4(float4 v, int d) {
    return make_float4(__shfl_down_sync(FULL, v.x, d),
                       __shfl_down_sync(FULL, v.y, d),
                       __shfl_down_sync(FULL, v.z, d),
                       __shfl_down_sync(FULL, v.w, d));
}

__global__ __launch_bounds__(128, 7)
void bkt_fused(const int* __restrict__ corr,
               const float* __restrict__ dyn,
               const float* __restrict__ obs,
               float* __restrict__ out)
{
    __shared__ float4 sWa[4];  __shared__ int sEWa[4];  // alpha warp-total matrices
    __shared__ float4 sWb[4];                            // beta warp-total matrices
    // output staging: stride 5 float4s per segment -> conflict-free STS/LDS.128
    __shared__ float4 sP4[SEG * 5];   // pred
    __shared__ float4 sQ4[SEG * 5];   // post
    __shared__ float4 sS4[SEG * 5];   // smoothed
    __shared__ float  sF[SEG * 9];    // f0 per (seg, step): stride 9 -> conflict-free

    const int k    = threadIdx.x;      // segment index in row
    const int lane = k & 31;
    const int w    = k >> 5;
    const int row  = blockIdx.x;

    // ---------------- load own segment (contiguous per warp) ----------------
    float o[2 * L];
    const float4* op = (const float4*)(obs + (size_t)row * (TT * 2) + k * (2 * L));
#pragma unroll
    for (int i = 0; i < 4; i++) {
        float4 v = op[i];
        o[4 * i + 0] = v.x; o[4 * i + 1] = v.y;
        o[4 * i + 2] = v.z; o[4 * i + 3] = v.w;
    }
    unsigned ymask = 0;
    const int4* cp = (const int4*)(corr + (size_t)row * TT + k * L);
#pragma unroll
    for (int i = 0; i < 2; i++) {
        int4 v = cp[i];
        ymask |= (unsigned)(v.x & 1) << (4 * i + 0);
        ymask |= (unsigned)(v.y & 1) << (4 * i + 1);
        ymask |= (unsigned)(v.z & 1) << (4 * i + 2);
        ymask |= (unsigned)(v.w & 1) << (4 * i + 3);
    }

    // per-row parameters (broadcast loads); shared rcp for the two trans sigmoids
    float d0 = dyn[row * 3 + 0];
    float d1 = dyn[row * 3 + 1];
    float d2 = dyn[row * 3 + 2];
    float ed0 = __expf(d0), ed1 = __expf(d1), ed2 = __expf(d2);
    float q0d = 1.f + ed0, q1d = 1.f + ed1;
    float rpd = frcp(q0d * q1d);
    float rr0 = rpd * q1d;            // 1/(1+ed0)
    float rr1 = rpd * q0d;            // 1/(1+ed1)
    float ri2 = frcp(1.f + ed2);
    float t00 = rr0,       t10 = ed0 * rr0;   // src=0 column (sums to 1)
    float t01 = ed1 * rr1, t11 = rr1;         // src=1 column (sums to 1)
    float ai0 = ri2, ai1 = ed2 * ri2;         // normalized alpha_init

    // ---------------- phase 1: emissions + segment 2x2 product ----------------
    float4 A = make_float4(1.f, 0.f, 0.f, 1.f);
#pragma unroll
    for (int j = 0; j < L; j++) {
        int y = (ymask >> j) & 1;
        float e0 = __expf(o[2 * j]), e1 = __expf(o[2 * j + 1]);
        float s0 = 1.f + e0, s1 = 1.f + e1;
        float rp = frcp(s0 * s1);
        float r0 = rp * s1;           // 1/(1+e0)
        float r1 = rp * s0;           // 1/(1+e1)
        float py0 = y ? e0 * r0 : r0;
        float py1 = y ? r1 : e1 * r1;
        o[2 * j]     = py0;           // keep emissions in registers
        o[2 * j + 1] = py1;

        float m00 = t00 * py0, m01 = t01 * py1;
        float m10 = t10 * py0, m11 = t11 * py1;
        A = make_float4(m00 * A.x + m01 * A.z,
                        m00 * A.y + m01 * A.w,
                        m10 * A.x + m11 * A.z,
                        m10 * A.y + m11 * A.w);
    }
    int Ea = 0;
    renormE(A, Ea);

    // ---------------- phase 2a: in-warp shuffle scans ----------------
    float4 va = A;  int ea = Ea;                     // prefix: va_k = A_k ... A_first
    float4 vb = make_float4(A.x, A.z, A.y, A.w);     // suffix of A^T
#pragma unroll
    for (int d = 1; d < 32; d <<= 1) {
        float4 na = shflup4(va, d);
        int   nea = __shfl_up_sync(FULL, ea, d);
        float4 nb = shfldn4(vb, d);
        if (lane >= d)      { va = mm2(va, na); ea += nea; renormE(va, ea); }
        if (lane + d < 32)  { vb = mm2(vb, nb); renormD(vb); }
    }
    if (lane == 31) { sWa[w] = va; sEWa[w] = ea; }
    if (lane == 0)  { sWb[w] = vb; }
    __syncthreads();

    // ---------------- phase 2b: cross-warp combine via matvecs ----------------
    float u0 = ai0, u1 = ai1; int Eu = 0;
#pragma unroll
    for (int i = 0; i < 3; i++) {
        if (i < w) {
            float4 W = sWa[i];
            float n0 = W.x * u0 + W.y * u1;
            float n1 = W.z * u0 + W.w * u1;
            float s  = n0 + n1;
            int eb = (__float_as_int(s) >> 23) & 0xFF;
            float sc = __int_as_float((254 - eb) << 23);
            u0 = n0 * sc; u1 = n1 * sc;
            Eu += sEWa[i] + (eb - 127);
        }
    }
    float wv0 = 1.f, wv1 = 1.f;
#pragma unroll
    for (int i = 3; i >= 1; i--) {
        if (i > w) {
            float4 W = sWb[i];
            float n0 = W.x * wv0 + W.y * wv1;
            float n1 = W.z * wv0 + W.w * wv1;
            float rs = frcp(n0 + n1);
            wv0 = n0 * rs; wv1 = n1 * rs;
        }
    }

    float4 exv = shflup4(va, 1);
    int    exe = __shfl_up_sync(FULL, ea, 1);
    float4 exb = shfldn4(vb, 1);

    float a0, a1, C;
    if (lane == 0) {
        float s  = u0 + u1;
        float rs = frcp(s);
        a0 = u0 * rs; a1 = u1 * rs;
        C = __logf(s) + (float)Eu * LN2F;
    } else {
        float v0 = exv.x * u0 + exv.y * u1;
        float v1 = exv.z * u0 + exv.w * u1;
        float s  = v0 + v1;
        float rs = frcp(s);
        a0 = v0 * rs; a1 = v1 * rs;
        C = __logf(s) + (float)(exe + Eu) * LN2F;
    }
    float b0, b1;
    if (lane == 31) {
        b0 = wv0; b1 = wv1;
    } else {
        b0 = exb.x * wv0 + exb.y * wv1;
        b1 = exb.z * wv0 + exb.w * wv1;
    }

    // ---------------- phase 3 fwd: pred + post + f0 (f0 -> smem) ----------------
    float hp0 = 0.f, hp1 = 0.f, hq0 = 0.f, hq1 = 0.f;
#pragma unroll
    for (int j = 0; j < L; j++) {
        int y = (ymask >> j) & 1;
        float py0 = o[2 * j];
        float py1 = o[2 * j + 1];

        float jj0 = a0 * py0;
        float jj1 = a1 * py1;
        float js  = jj0 + jj1;           // predictive prob of observed symbol
        float ljs = __logf(js);
        float lns = __logf(1.f - js);    // predictive probs sum to 1 (a normalized)
        float lp0 = y ? lns : ljs;
        float lp1 = y ? ljs : lns;
        float po0 = __logf(jj0) + C;
        float po1 = __logf(jj1) + C;

        float f  = jj0 * frcp(js);
        sF[k * 9 + j] = f;               // off critical chain; conflict-free
        float fc = 1.f - f;
        a0 = t00 * f + t01 * fc;         // stays normalized (T columns sum to 1)
        a1 = t10 * f + t11 * fc;
        C += ljs;

        if ((j & 1) == 0) {
            hp0 = lp0; hp1 = lp1; hq0 = po0; hq1 = po1;
        } else {
            sP4[k * 5 + (j >> 1)] = make_float4(hp0, hp1, lp0, lp1);
            sQ4[k * 5 + (j >> 1)] = make_float4(hq0, hq1, po0, po1);
        }
    }
    __syncthreads();

    // ---------------- early flush of pred+post (overlaps with bwd below) ----------------
    float4* dP = (float4*)(out + (size_t)row * (TT * 2));
    float4* dQ = (float4*)(out + (size_t)BN * TT * 2 + (size_t)row * (TT * 2));
#pragma unroll
    for (int i = 0; i < 4; i++) {
        int G = i * 128 + k;             // float4 index within the row (0..511)
        int m = (G >> 2) * 5 + (G & 3);
        dP[G] = sP4[m];
        dQ[G] = sQ4[m];
    }

    // ---------------- phase 3 bwd: smoothed ----------------
    float hs0 = 0.f, hs1 = 0.f;
#pragma unroll
    for (int j = L - 1; j >= 0; j--) {
        float f  = sF[k * 9 + j];
        float fc = 1.f - f;
        float g0 = f  * b0;
        float g1 = fc * b1;
        float rg = frcp(g0 + g1);
        float s0 = __logf(g0 * rg);
        float s1 = __logf(g1 * rg);

        if (j & 1) {
            hs0 = s0; hs1 = s1;
        } else {
            sS4[k * 5 + (j >> 1)] = make_float4(s0, s1, hs0, hs1);
        }

        float u0b = o[2 * j]     * b0;
        float u1b = o[2 * j + 1] * b1;
        b0 = t00 * u0b + t10 * u1b;      // beta to t-1 (no rescale needed over 8 steps)
        b1 = t01 * u0b + t11 * u1b;
    }
    __syncthreads();

    // ---------------- flush smoothed ----------------
    float4* dS = (float4*)(out + (size_t)2 * BN * TT * 2 + (size_t)row * (TT * 2));
#pragma unroll
    for (int i = 0; i < 4; i++) {
        int G = i * 128 + k;
        int m = (G >> 2) * 5 + (G & 3);
        dS[G] = sS4[m];
    }
}

extern "C" void kernel_launch(void* const* d_in, const int* in_sizes, int n_in,
                              void* d_out, int out_size)
{
    const int*   corr = (const int*)d_in[0];
    const float* dyn  = (const float*)d_in[1];
    const float* obs  = (const float*)d_in[2];
    float* out = (float*)d_out;

    bkt_fused<<<BN, 128>>>(corr, dyn, obs, out);
}

// round 17
// speedup vs baseline: 1.1269x; 1.0388x over previous
#include <cuda_runtime.h>
#include <cstdint>

// BKT 2-state HMM forward-backward, FULLY FUSED: one block = one row.
// Warp-shuffle Kogge-Stone over 128 time segments (L=8 steps each).
// Two staging planes only: smoothed reuses the pred plane after its early
// flush -> 25KB smem -> 7 blocks/SM (28 warps).
// corr: (B,T) int32 ; dynamics_logits: (B,3) f32 ; obs_logits: (B,T,2) f32
// out: (3,B,T,2) f32 = [output_logprobs, state_posteriors, smoothed]

#define BN   8192
#define TT   1024
#define SEG  128
#define L    8
#define LN2F 0.69314718055994531f
#define FULL 0xFFFFFFFFu

__device__ __forceinline__ float frcp(float x) {
    float r;
    asm("rcp.approx.f32 %0, %1;" : "=f"(r) : "f"(x));
    return r;
}

// 2x2 matmul, layout x=m00 y=m01 z=m10 w=m11 ; returns A*B
__device__ __forceinline__ float4 mm2(float4 A, float4 B) {
    return make_float4(A.x * B.x + A.y * B.z,
                       A.x * B.y + A.y * B.w,
                       A.z * B.x + A.w * B.z,
                       A.z * B.y + A.w * B.w);
}

__device__ __forceinline__ void renormE(float4& M, int& E) {
    float s = (M.x + M.y) + (M.z + M.w);
    int eb = (__float_as_int(s) >> 23) & 0xFF;
    float sc = __int_as_float((254 - eb) << 23);
    M.x *= sc; M.y *= sc; M.z *= sc; M.w *= sc;
    E += eb - 127;
}
__device__ __forceinline__ void renormD(float4& M) {
    float s = (M.x + M.y) + (M.z + M.w);
    int eb = (__float_as_int(s) >> 23) & 0xFF;
    float sc = __int_as_float((254 - eb) << 23);
    M.x *= sc; M.y *= sc; M.z *= sc; M.w *= sc;
}

__device__ __forceinline__ float4 shflup4(float4 v, int d) {
    return make_float4(__shfl_up_sync(FULL, v.x, d),
                       __shfl_up_sync(FULL, v.y, d),
                       __shfl_up_sync(FULL, v.z, d),
                       __shfl_up_sync(FULL, v.w, d));
}
__device__ __forceinline__ float4 shfldn4(float4 v, int d) {
    return make_float4(__shfl_down_sync(FULL, v.x, d),
                       __shfl_down_sync(FULL, v.y, d),
                       __shfl_down_sync(FULL, v.z, d),
                       __shfl_down_sync(FULL, v.w, d));
}

__global__ __launch_bounds__(128, 7)
void bkt_fused(const int* __restrict__ corr,
               const float* __restrict__ dyn,
               const float* __restrict__ obs,
               float* __restrict__ out)
{
    __shared__ float4 sWa[4];  __shared__ int sEWa[4];  // alpha warp-total matrices
    __shared__ float4 sWb[4];                            // beta warp-total matrices
    // staging: stride 5 float4s per segment -> conflict-free STS/LDS.128
    __shared__ float4 sP4[SEG * 5];   // pred, then reused for smoothed
    __shared__ float4 sQ4[SEG * 5];   // post
    __shared__ float  sF[SEG * 9];    // f0 per (seg, step): stride 9 -> conflict-free

    const int k    = threadIdx.x;      // segment index in row
    const int lane = k & 31;
    const int w    = k >> 5;
    const int row  = blockIdx.x;

    // ---------------- load own segment (contiguous per warp) ----------------
    float o[2 * L];
    const float4* op = (const float4*)(obs + (size_t)row * (TT * 2) + k * (2 * L));
#pragma unroll
    for (int i = 0; i < 4; i++) {
        float4 v = op[i];
        o[4 * i + 0] = v.x; o[4 * i + 1] = v.y;
        o[4 * i + 2] = v.z; o[4 * i + 3] = v.w;
    }
    unsigned ymask = 0;
    const int4* cp = (const int4*)(corr + (size_t)row * TT + k * L);
#pragma unroll
    for (int i = 0; i < 2; i++) {
        int4 v = cp[i];
        ymask |= (unsigned)(v.x & 1) << (4 * i + 0);
        ymask |= (unsigned)(v.y & 1) << (4 * i + 1);
        ymask |= (unsigned)(v.z & 1) << (4 * i + 2);
        ymask |= (unsigned)(v.w & 1) << (4 * i + 3);
    }

    // per-row parameters (broadcast loads); shared rcp for the two trans sigmoids
    float d0 = dyn[row * 3 + 0];
    float d1 = dyn[row * 3 + 1];
    float d2 = dyn[row * 3 + 2];
    float ed0 = __expf(d0), ed1 = __expf(d1), ed2 = __expf(d2);
    float q0d = 1.f + ed0, q1d = 1.f + ed1;
    float rpd = frcp(q0d * q1d);
    float rr0 = rpd * q1d;            // 1/(1+ed0)
    float rr1 = rpd * q0d;            // 1/(1+ed1)
    float ri2 = frcp(1.f + ed2);
    float t00 = rr0,       t10 = ed0 * rr0;   // src=0 column (sums to 1)
    float t01 = ed1 * rr1, t11 = rr1;         // src=1 column (sums to 1)
    float ai0 = ri2, ai1 = ed2 * ri2;         // normalized alpha_init

    // ---------------- phase 1: emissions + segment 2x2 product ----------------
    float4 A = make_float4(1.f, 0.f, 0.f, 1.f);
#pragma unroll
    for (int j = 0; j < L; j++) {
        int y = (ymask >> j) & 1;
        float e0 = __expf(o[2 * j]), e1 = __expf(o[2 * j + 1]);
        float s0 = 1.f + e0, s1 = 1.f + e1;
        float rp = frcp(s0 * s1);
        float r0 = rp * s1;           // 1/(1+e0)
        float r1 = rp * s0;           // 1/(1+e1)
        float py0 = y ? e0 * r0 : r0;
        float py1 = y ? r1 : e1 * r1;
        o[2 * j]     = py0;           // keep emissions in registers
        o[2 * j + 1] = py1;

        float m00 = t00 * py0, m01 = t01 * py1;
        float m10 = t10 * py0, m11 = t11 * py1;
        A = make_float4(m00 * A.x + m01 * A.z,
                        m00 * A.y + m01 * A.w,
                        m10 * A.x + m11 * A.z,
                        m10 * A.y + m11 * A.w);
    }
    int Ea = 0;
    renormE(A, Ea);

    // ---------------- phase 2a: in-warp shuffle scans ----------------
    float4 va = A;  int ea = Ea;                     // prefix: va_k = A_k ... A_first
    float4 vb = make_float4(A.x, A.z, A.y, A.w);     // suffix of A^T
#pragma unroll
    for (int d = 1; d < 32; d <<= 1) {
        float4 na = shflup4(va, d);
        int   nea = __shfl_up_sync(FULL, ea, d);
        float4 nb = shfldn4(vb, d);
        if (lane >= d)      { va = mm2(va, na); ea += nea; renormE(va, ea); }
        if (lane + d < 32)  { vb = mm2(vb, nb); renormD(vb); }
    }
    if (lane == 31) { sWa[w] = va; sEWa[w] = ea; }
    if (lane == 0)  { sWb[w] = vb; }
    __syncthreads();

    // ---------------- phase 2b: cross-warp combine via matvecs ----------------
    float u0 = ai0, u1 = ai1; int Eu = 0;
#pragma unroll
    for (int i = 0; i < 3; i++) {
        if (i < w) {
            float4 W = sWa[i];
            float n0 = W.x * u0 + W.y * u1;
            float n1 = W.z * u0 + W.w * u1;
            float s  = n0 + n1;
            int eb = (__float_as_int(s) >> 23) & 0xFF;
            float sc = __int_as_float((254 - eb) << 23);
            u0 = n0 * sc; u1 = n1 * sc;
            Eu += sEWa[i] + (eb - 127);
        }
    }
    float wv0 = 1.f, wv1 = 1.f;
#pragma unroll
    for (int i = 3; i >= 1; i--) {
        if (i > w) {
            float4 W = sWb[i];
            float n0 = W.x * wv0 + W.y * wv1;
            float n1 = W.z * wv0 + W.w * wv1;
            float rs = frcp(n0 + n1);
            wv0 = n0 * rs; wv1 = n1 * rs;
        }
    }

    float4 exv = shflup4(va, 1);
    int    exe = __shfl_up_sync(FULL, ea, 1);
    float4 exb = shfldn4(vb, 1);

    float a0, a1, C;
    if (lane == 0) {
        float s  = u0 + u1;
        float rs = frcp(s);
        a0 = u0 * rs; a1 = u1 * rs;
        C = __logf(s) + (float)Eu * LN2F;
    } else {
        float v0 = exv.x * u0 + exv.y * u1;
        float v1 = exv.z * u0 + exv.w * u1;
        float s  = v0 + v1;
        float rs = frcp(s);
        a0 = v0 * rs; a1 = v1 * rs;
        C = __logf(s) + (float)(exe + Eu) * LN2F;
    }
    float b0, b1;
    if (lane == 31) {
        b0 = wv0; b1 = wv1;
    } else {
        b0 = exb.x * wv0 + exb.y * wv1;
        b1 = exb.z * wv0 + exb.w * wv1;
    }

    // ---------------- phase 3 fwd: pred + post + f0 (f0 -> smem) ----------------
    float hp0 = 0.f, hp1 = 0.f, hq0 = 0.f, hq1 = 0.f;
#pragma unroll
    for (int j = 0; j < L; j++) {
        int y = (ymask >> j) & 1;
        float py0 = o[2 * j];
        float py1 = o[2 * j + 1];

        float jj0 = a0 * py0;
        float jj1 = a1 * py1;
        float js  = jj0 + jj1;           // predictive prob of observed symbol
        float ljs = __logf(js);
        float lns = __logf(1.f - js);    // predictive probs sum to 1 (a normalized)
        float lp0 = y ? lns : ljs;
        float lp1 = y ? ljs : lns;
        float po0 = __logf(jj0) + C;
        float po1 = __logf(jj1) + C;

        float f  = jj0 * frcp(js);
        sF[k * 9 + j] = f;               // off critical chain; conflict-free
        float fc = 1.f - f;
        a0 = t00 * f + t01 * fc;         // stays normalized (T columns sum to 1)
        a1 = t10 * f + t11 * fc;
        C += ljs;

        if ((j & 1) == 0) {
            hp0 = lp0; hp1 = lp1; hq0 = po0; hq1 = po1;
        } else {
            sP4[k * 5 + (j >> 1)] = make_float4(hp0, hp1, lp0, lp1);
            sQ4[k * 5 + (j >> 1)] = make_float4(hq0, hq1, po0, po1);
        }
    }
    __syncthreads();

    // ---------------- early flush of pred+post (overlaps with bwd below) ----------------
    float4* dP = (float4*)(out + (size_t)row * (TT * 2));
    float4* dQ = (float4*)(out + (size_t)BN * TT * 2 + (size_t)row * (TT * 2));
#pragma unroll
    for (int i = 0; i < 4; i++) {
        int G = i * 128 + k;             // float4 index within the row (0..511)
        int m = (G >> 2) * 5 + (G & 3);
        dP[G] = sP4[m];
        dQ[G] = sQ4[m];
    }
    __syncthreads();                     // protect sP4 reuse (flush reads done)

    // ---------------- phase 3 bwd: smoothed (staged into sP4) ----------------
    float hs0 = 0.f, hs1 = 0.f;
#pragma unroll
    for (int j = L - 1; j >= 0; j--) {
        float f  = sF[k * 9 + j];
        float fc = 1.f - f;
        float g0 = f  * b0;
        float g1 = fc * b1;
        float rg = frcp(g0 + g1);
        float s0 = __logf(g0 * rg);
        float s1 = __logf(g1 * rg);

        if (j & 1) {
            hs0 = s0; hs1 = s1;
        } else {
            sP4[k * 5 + (j >> 1)] = make_float4(s0, s1, hs0, hs1);
        }

        float u0b = o[2 * j]     * b0;
        float u1b = o[2 * j + 1] * b1;
        b0 = t00 * u0b + t10 * u1b;      // beta to t-1 (no rescale needed over 8 steps)
        b1 = t01 * u0b + t11 * u1b;
    }
    __syncthreads();

    // ---------------- flush smoothed ----------------
    float4* dS = (float4*)(out + (size_t)2 * BN * TT * 2 + (size_t)row * (TT * 2));
#pragma unroll
    for (int i = 0; i < 4; i++) {
        int G = i * 128 + k;
        int m = (G >> 2) * 5 + (G & 3);
        dS[G] = sP4[m];
    }
}

extern "C" void kernel_launch(void* const* d_in, const int* in_sizes, int n_in,
                              void* d_out, int out_size)
{
    const int*   corr = (const int*)d_in[0];
    const float* dyn  = (const float*)d_in[1];
    const float* obs  = (const float*)d_in[2];
    float* out = (float*)d_out;

    bkt_fused<<<BN, 128>>>(corr, dyn, obs, out);
}